// round 4
// baseline (speedup 1.0000x reference)
#include <cuda_runtime.h>
#include <cuda_fp16.h>
#include <mma.h>
#include <math.h>

using namespace nvcuda;

#define N_NODES 40000
#define E_EDGES 640000
#define IN_F 128
#define OUT_F 32
#define HEADS 8
#define MCOLS (HEADS * OUT_F)   // 256

// Scratch (static device globals; no allocation allowed)
__device__ __half g_Mh[N_NODES * MCOLS];      // h @ W_msg[:128] fp16 (20.5 MB, L2-resident)
__device__ float g_asrc[N_NODES * HEADS];
__device__ float g_adst[N_NODES * HEADS];
__device__ float g_attn[E_EDGES * HEADS];     // exp(score) in CSR (dst-grouped) order
__device__ int   g_src[E_EDGES];              // src node per CSR slot
__device__ float g_ex[E_EDGES];               // edge feat per CSR slot
__device__ int   g_cnt[N_NODES];              // in-degree histogram
__device__ int   g_off[N_NODES + 1];          // CSR offsets
__device__ int   g_cur[N_NODES];              // scatter cursors
__device__ float g_csrc[IN_F * HEADS];
__device__ float g_cdst[IN_F * HEADS];

// ---------------------------------------------------------------------------
__global__ void k_init() {
    int i = blockIdx.x * blockDim.x + threadIdx.x;
    if (i < N_NODES) g_cnt[i] = 0;
}

// ---------------------------------------------------------------------------
// fold W_node with attention vectors: c[i,h] = sum_f W_node[i, h*32+f] * att[h,f]
__global__ void k_coef(const float* __restrict__ Wn,
                       const float* __restrict__ att_s,
                       const float* __restrict__ att_d) {
    int t = threadIdx.x;             // 1024 threads: t = i*8 + h
    int i = t >> 3, hh = t & 7;
    float s1 = 0.f, s2 = 0.f;
    #pragma unroll
    for (int f = 0; f < OUT_F; f++) {
        float w = Wn[i * MCOLS + hh * OUT_F + f];
        s1 += w * att_s[hh * OUT_F + f];
        s2 += w * att_d[hh * OUT_F + f];
    }
    g_csrc[t] = s1;
    g_cdst[t] = s2;
}

// ---------------------------------------------------------------------------
// per-node attention pre-scores: a_src = h @ c_src, a_dst = h @ c_dst
__global__ void k_anode(const float* __restrict__ h) {
    __shared__ float cs[IN_F * HEADS];
    __shared__ float cd[IN_F * HEADS];
    int tid = threadIdx.x;
    for (int i = tid; i < IN_F * HEADS; i += blockDim.x) {
        cs[i] = g_csrc[i];
        cd[i] = g_cdst[i];
    }
    __syncthreads();
    int idx = blockIdx.x * blockDim.x + tid;
    if (idx >= N_NODES * HEADS) return;
    int n = idx >> 3, hh = idx & 7;
    const float* hr = h + (size_t)n * IN_F;
    float s1 = 0.f, s2 = 0.f;
    #pragma unroll 8
    for (int i = 0; i < IN_F; i++) {
        float hv = hr[i];
        s1 += hv * cs[i * HEADS + hh];
        s2 += hv * cd[i * HEADS + hh];
    }
    g_asrc[idx] = s1;
    g_adst[idx] = s2;
}

// ---------------------------------------------------------------------------
// Tensor-core GEMM: M[40000,256] = h[40000,128] @ W_msg[0:128,0:256], fp16 out.
// BM=64, BN=256, BK=32; 8 warps in 2(M)x4(N) layout, each warp 32x64 via
// 2x4 wmma 16x16x16 fragments (fp16 in, fp32 accumulate).
__global__ void __launch_bounds__(256) k_gemm(const float* __restrict__ h,
                                              const float* __restrict__ Wm) {
    __shared__ __align__(32) __half Ah[64][48];    // stride 96B (mult of 32)
    __shared__ __align__(32) __half Bh[32][272];   // stride 544B (mult of 32)
    __shared__ float Cst[8][16][16];               // per-warp epilogue staging
    int tid = threadIdx.x;
    int wid = tid >> 5, lane = tid & 31;
    int wm = wid >> 2;          // 0..1
    int wn = wid & 3;           // 0..3
    int m0 = blockIdx.x * 64;   // 625 blocks exact

    wmma::fragment<wmma::accumulator, 16, 16, 16, float> c[2][4];
    #pragma unroll
    for (int i = 0; i < 2; i++)
        #pragma unroll
        for (int j = 0; j < 4; j++) wmma::fill_fragment(c[i][j], 0.f);

    int ar = tid >> 2;               // 0..63
    int ac = (tid & 3) * 8;          // 0,8,16,24
    int br = tid >> 3;               // 0..31
    int bc = (tid & 7) * 32;         // 0..224

    for (int k0 = 0; k0 < IN_F; k0 += 32) {
        // A tile 64x32: fp32 -> fp16
        const float* ag = h + (size_t)(m0 + ar) * IN_F + k0 + ac;
        float4 v0 = *(const float4*)ag;
        float4 v1 = *(const float4*)(ag + 4);
        __half2* ap = (__half2*)&Ah[ar][ac];
        ap[0] = __floats2half2_rn(v0.x, v0.y);
        ap[1] = __floats2half2_rn(v0.z, v0.w);
        ap[2] = __floats2half2_rn(v1.x, v1.y);
        ap[3] = __floats2half2_rn(v1.z, v1.w);
        // B tile 32x256: fp32 -> fp16
        const float* bg = Wm + (size_t)(k0 + br) * MCOLS + bc;
        __half2* bp = (__half2*)&Bh[br][bc];
        #pragma unroll
        for (int q = 0; q < 8; q++) {
            float4 bv = *(const float4*)(bg + q * 4);
            bp[q * 2]     = __floats2half2_rn(bv.x, bv.y);
            bp[q * 2 + 1] = __floats2half2_rn(bv.z, bv.w);
        }
        __syncthreads();
        #pragma unroll
        for (int kk = 0; kk < 32; kk += 16) {
            wmma::fragment<wmma::matrix_a, 16, 16, 16, __half, wmma::row_major> af[2];
            wmma::fragment<wmma::matrix_b, 16, 16, 16, __half, wmma::row_major> bf[4];
            #pragma unroll
            for (int i = 0; i < 2; i++)
                wmma::load_matrix_sync(af[i], &Ah[wm * 32 + i * 16][kk], 48);
            #pragma unroll
            for (int j = 0; j < 4; j++)
                wmma::load_matrix_sync(bf[j], &Bh[kk][wn * 64 + j * 16], 272);
            #pragma unroll
            for (int i = 0; i < 2; i++)
                #pragma unroll
                for (int j = 0; j < 4; j++)
                    wmma::mma_sync(c[i][j], af[i], bf[j], c[i][j]);
        }
        __syncthreads();
    }
    // epilogue: per-fragment fp32 staging -> fp16 global
    int rr = lane >> 1, cc = (lane & 1) * 8;
    #pragma unroll
    for (int i = 0; i < 2; i++)
        #pragma unroll
        for (int j = 0; j < 4; j++) {
            wmma::store_matrix_sync(&Cst[wid][0][0], c[i][j], 16, wmma::mem_row_major);
            __syncwarp();
            const float* sp = &Cst[wid][rr][cc];
            __half2 hv[4];
            #pragma unroll
            for (int q = 0; q < 4; q++)
                hv[q] = __floats2half2_rn(sp[q * 2], sp[q * 2 + 1]);
            int grow = m0 + wm * 32 + i * 16 + rr;
            int gcol = wn * 64 + j * 16 + cc;
            *(uint4*)(g_Mh + (size_t)grow * MCOLS + gcol) = *(uint4*)hv;
            __syncwarp();
        }
}

// ---------------------------------------------------------------------------
// in-degree histogram
__global__ void k_hist(const int* __restrict__ ei) {
    int e = blockIdx.x * blockDim.x + threadIdx.x;
    if (e < E_EDGES) atomicAdd(&g_cnt[ei[E_EDGES + e]], 1);
}

// ---------------------------------------------------------------------------
// exclusive scan of g_cnt -> g_off, g_cur. Single block, 1024 threads x 40.
__global__ void k_scan() {
    __shared__ int part[1024];
    int t = threadIdx.x;
    int base = t * 40;
    int s = 0;
    #pragma unroll 8
    for (int i = 0; i < 40; i++) {
        int idx = base + i;
        s += (idx < N_NODES) ? g_cnt[idx] : 0;
    }
    part[t] = s;
    __syncthreads();
    for (int off = 1; off < 1024; off <<= 1) {
        int v = (t >= off) ? part[t - off] : 0;
        __syncthreads();
        part[t] += v;
        __syncthreads();
    }
    int run = (t > 0) ? part[t - 1] : 0;
    for (int i = 0; i < 40; i++) {
        int idx = base + i;
        if (idx < N_NODES) {
            g_off[idx] = run;
            g_cur[idx] = run;
            run += g_cnt[idx];
        }
    }
    if (t == 1023) g_off[N_NODES] = part[1023];
}

// ---------------------------------------------------------------------------
// edge pass: score -> leaky relu -> exp (no max shift; bounded scores) and
// scatter (p[8], src, x) into the dst-grouped CSR slot.
__global__ void k_score(const int* __restrict__ ei, const float* __restrict__ ef,
                        const float* __restrict__ We) {
    int e = blockIdx.x * blockDim.x + threadIdx.x;
    if (e >= E_EDGES) return;
    int s = ei[e];
    int d = ei[E_EDGES + e];
    float x = ef[e];

    float4 sa0 = *(const float4*)&g_asrc[s * HEADS];
    float4 sa1 = *(const float4*)&g_asrc[s * HEADS + 4];
    float4 da0 = *(const float4*)&g_adst[d * HEADS];
    float4 da1 = *(const float4*)&g_adst[d * HEADS + 4];
    float sv[8] = {sa0.x, sa0.y, sa0.z, sa0.w, sa1.x, sa1.y, sa1.z, sa1.w};
    float dv[8] = {da0.x, da0.y, da0.z, da0.w, da1.x, da1.y, da1.z, da1.w};

    float p[8];
    #pragma unroll
    for (int hh = 0; hh < HEADS; hh++) {
        float a = sv[hh] + dv[hh] + x * __ldg(&We[hh]);
        a = (a > 0.f) ? a : 0.2f * a;          // leaky relu
        p[hh] = __expf(a);
    }
    int pos = atomicAdd(&g_cur[d], 1);
    float* ap = &g_attn[(size_t)pos * HEADS];
    *(float4*)ap       = make_float4(p[0], p[1], p[2], p[3]);
    *(float4*)(ap + 4) = make_float4(p[4], p[5], p[6], p[7]);
    g_src[pos] = s;
    g_ex[pos]  = x;
}

// ---------------------------------------------------------------------------
// warp per destination node, lane = output feature. No atomics: local softmax
// denominator + per-head register accumulation, one coalesced store per node.
__global__ void k_out(const float* __restrict__ Wm, float* __restrict__ out) {
    int d = (blockIdx.x * blockDim.x + threadIdx.x) >> 5;
    int lane = threadIdx.x & 31;
    if (d >= N_NODES) return;
    int beg = g_off[d], end = g_off[d + 1];

    const float* Wlast = Wm + (size_t)IN_F * MCOLS;   // W_msg edge-feat row
    float wreg[HEADS];
    #pragma unroll
    for (int hh = 0; hh < HEADS; hh++) wreg[hh] = Wlast[hh * OUT_F + lane];

    float acc[HEADS], psum[HEADS];
    #pragma unroll
    for (int hh = 0; hh < HEADS; hh++) { acc[hh] = 0.f; psum[hh] = 0.f; }

    for (int j = beg; j < end; j++) {
        float pl = (lane < HEADS) ? g_attn[(size_t)j * HEADS + lane] : 0.f;
        int s = g_src[j];
        float x = g_ex[j];
        const __half* Mrow = g_Mh + (size_t)s * MCOLS;
        #pragma unroll
        for (int hh = 0; hh < HEADS; hh++) {
            float a = __shfl_sync(0xffffffffu, pl, hh);
            psum[hh] += a;
            float mv = __half2float(Mrow[hh * OUT_F + lane]);
            acc[hh] = fmaf(a, fmaf(x, wreg[hh], mv), acc[hh]);
        }
    }
    float res = 0.f;
    #pragma unroll
    for (int hh = 0; hh < HEADS; hh++)
        res += __fdividef(acc[hh], fmaxf(psum[hh], 1e-12f));
    out[d * OUT_F + lane] = res * 0.125f;
}

// ---------------------------------------------------------------------------
extern "C" void kernel_launch(void* const* d_in, const int* in_sizes, int n_in,
                              void* d_out, int out_size) {
    const float* h   = (const float*)d_in[0];
    const int*   ei  = (const int*)d_in[1];
    const float* ef  = (const float*)d_in[2];
    const float* Wn  = (const float*)d_in[3];
    const float* We  = (const float*)d_in[4];
    const float* Asw = (const float*)d_in[5];
    const float* Adw = (const float*)d_in[6];
    const float* Wm  = (const float*)d_in[7];
    float* out = (float*)d_out;

    k_init<<<(N_NODES + 255) / 256, 256>>>();
    k_coef<<<1, 1024>>>(Wn, Asw, Adw);
    k_anode<<<(N_NODES * HEADS + 255) / 256, 256>>>(h);
    k_gemm<<<N_NODES / 64, 256>>>(h, Wm);
    k_hist<<<(E_EDGES + 255) / 256, 256>>>(ei);
    k_scan<<<1, 1024>>>();
    k_score<<<(E_EDGES + 255) / 256, 256>>>(ei, ef, We);
    k_out<<<(N_NODES * 32 + 255) / 256, 256>>>(Wm, out);
}